// round 8
// baseline (speedup 1.0000x reference)
#include <cuda_runtime.h>
#include <cuda_bf16.h>
#include <cuda_fp16.h>
#include <math.h>

#define NMAX 50000
#define EMAX 800000
#define ETOTMAX (NMAX + EMAX)
#define IN_DIM 128
#define HC 256
#define HEADS 4
#define CDIM 64
#define NEG_SLOPE 0.2f

// ---------------- scratch ----------------
__device__ __half d_hh[(size_t)NMAX * HC];      // projected features fp16 [N, 256]
__device__ float d_asrc[NMAX * HEADS];
__device__ float d_adst[NMAX * HEADS];
__device__ float d_e[(size_t)ETOTMAX * HEADS];  // per-edge exp(logit), CSR order
__device__ int d_deg[NMAX];
__device__ int d_ptr[NMAX];
__device__ int d_work[NMAX];
__device__ int d_csr_src[ETOTMAX];

__device__ __forceinline__ float lrelu(float v) {
    return v > 0.0f ? v : NEG_SLOPE * v;
}

// ---------------- Kernel 1: SGEMM h = x @ W (FFMA2, 128x64 tile, dbuf) ---------
// (proven r5 version: 8x4 microtile, M-paired FFMA2 accumulators)
#define BM 128
#define BN 64
#define BK 16
#define NKT (IN_DIM / BK)

__global__ void gemm_kernel(const float* __restrict__ A, const float* __restrict__ B,
                            const float* __restrict__ att_src,
                            const float* __restrict__ att_dst, int M) {
    __shared__ float As[2][BK][BM];
    __shared__ float Bs[2][BK][BN];

    int bx = blockIdx.x;             // head (BN == CDIM)
    int by = blockIdx.y;
    int tid = threadIdx.x;
    int tx = tid & 15;
    int ty = tid >> 4;
    int row0 = by * BM;
    int col0 = bx * BN;

    unsigned long long acc[4][4];
    #pragma unroll
    for (int i = 0; i < 4; i++)
        #pragma unroll
        for (int j = 0; j < 4; j++) acc[i][j] = 0ULL;

    int ar = tid >> 1;
    int ac0 = (tid & 1) * 8;
    int br = tid >> 4;
    int bc = (tid & 15) * 4;

    float4 pa0, pa1, pb;

    {
        int grow = row0 + ar;
        if (grow < M) {
            pa0 = *(const float4*)(A + (size_t)grow * IN_DIM + ac0);
            pa1 = *(const float4*)(A + (size_t)grow * IN_DIM + ac0 + 4);
        } else {
            pa0 = make_float4(0.f, 0.f, 0.f, 0.f);
            pa1 = pa0;
        }
        pb = *(const float4*)(B + (size_t)br * HC + col0 + bc);
    }
    As[0][ac0 + 0][ar] = pa0.x; As[0][ac0 + 1][ar] = pa0.y;
    As[0][ac0 + 2][ar] = pa0.z; As[0][ac0 + 3][ar] = pa0.w;
    As[0][ac0 + 4][ar] = pa1.x; As[0][ac0 + 5][ar] = pa1.y;
    As[0][ac0 + 6][ar] = pa1.z; As[0][ac0 + 7][ar] = pa1.w;
    *(float4*)(&Bs[0][br][bc]) = pb;
    __syncthreads();

    #pragma unroll
    for (int kt = 0; kt < NKT; kt++) {
        int cur = kt & 1;
        if (kt < NKT - 1) {
            int k0 = (kt + 1) * BK;
            int grow = row0 + ar;
            if (grow < M) {
                pa0 = *(const float4*)(A + (size_t)grow * IN_DIM + k0 + ac0);
                pa1 = *(const float4*)(A + (size_t)grow * IN_DIM + k0 + ac0 + 4);
            } else {
                pa0 = make_float4(0.f, 0.f, 0.f, 0.f);
                pa1 = pa0;
            }
            pb = *(const float4*)(B + (size_t)(k0 + br) * HC + col0 + bc);
        }

        #pragma unroll
        for (int k = 0; k < BK; k++) {
            const ulonglong2* ap = (const ulonglong2*)(&As[cur][k][ty * 8]);
            ulonglong2 a01 = ap[0];
            ulonglong2 a23 = ap[1];
            unsigned long long a64[4] = {a01.x, a01.y, a23.x, a23.y};
            float4 b4 = *(const float4*)(&Bs[cur][k][tx * 4]);
            float bb[4] = {b4.x, b4.y, b4.z, b4.w};
            unsigned long long bp[4];
            #pragma unroll
            for (int j = 0; j < 4; j++)
                asm("mov.b64 %0, {%1, %1};" : "=l"(bp[j]) : "f"(bb[j]));
            #pragma unroll
            for (int i2 = 0; i2 < 4; i2++)
                #pragma unroll
                for (int j = 0; j < 4; j++)
                    asm("fma.rn.f32x2 %0, %1, %2, %0;"
                        : "+l"(acc[i2][j]) : "l"(a64[i2]), "l"(bp[j]));
        }

        if (kt < NKT - 1) {
            int nb = cur ^ 1;
            As[nb][ac0 + 0][ar] = pa0.x; As[nb][ac0 + 1][ar] = pa0.y;
            As[nb][ac0 + 2][ar] = pa0.z; As[nb][ac0 + 3][ar] = pa0.w;
            As[nb][ac0 + 4][ar] = pa1.x; As[nb][ac0 + 5][ar] = pa1.y;
            As[nb][ac0 + 6][ar] = pa1.z; As[nb][ac0 + 7][ar] = pa1.w;
            *(float4*)(&Bs[nb][br][bc]) = pb;
            __syncthreads();
        }
    }

    float accf[8][4];
    #pragma unroll
    for (int i2 = 0; i2 < 4; i2++)
        #pragma unroll
        for (int j = 0; j < 4; j++) {
            float lo, hi;
            asm("mov.b64 {%0, %1}, %2;" : "=f"(lo), "=f"(hi) : "l"(acc[i2][j]));
            accf[2 * i2][j] = lo;
            accf[2 * i2 + 1][j] = hi;
        }

    #pragma unroll
    for (int rr = 0; rr < 8; rr++) {
        int grow = row0 + ty * 8 + rr;
        if (grow < M) {
            __half2 p0 = __floats2half2_rn(accf[rr][0], accf[rr][1]);
            __half2 p1 = __floats2half2_rn(accf[rr][2], accf[rr][3]);
            uint2 pk;
            pk.x = *(unsigned*)&p0;
            pk.y = *(unsigned*)&p1;
            *(uint2*)(d_hh + (size_t)grow * HC + col0 + tx * 4) = pk;
        }
    }

    int head = bx;
    float sw[4], dw[4];
    #pragma unroll
    for (int j = 0; j < 4; j++) {
        sw[j] = __ldg(&att_src[head * CDIM + tx * 4 + j]);
        dw[j] = __ldg(&att_dst[head * CDIM + tx * 4 + j]);
    }
    #pragma unroll
    for (int rr = 0; rr < 8; rr++) {
        float s = accf[rr][0] * sw[0] + accf[rr][1] * sw[1]
                + accf[rr][2] * sw[2] + accf[rr][3] * sw[3];
        float dd = accf[rr][0] * dw[0] + accf[rr][1] * dw[1]
                 + accf[rr][2] * dw[2] + accf[rr][3] * dw[3];
        #pragma unroll
        for (int o = 1; o < 16; o <<= 1) {
            s  += __shfl_xor_sync(0xFFFFFFFFu, s, o);
            dd += __shfl_xor_sync(0xFFFFFFFFu, dd, o);
        }
        int grow = row0 + ty * 8 + rr;
        if (tx == 0 && grow < M) {
            d_asrc[grow * HEADS + head] = s;
            d_adst[grow * HEADS + head] = dd;
        }
    }
}

// ---------------- CSR build ------------------------------------------------------
__global__ void deg_init_kernel(int N) {
    int i = blockIdx.x * blockDim.x + threadIdx.x;
    if (i < N) d_deg[i] = 0;
}

__global__ void deg_hist_kernel(const int* __restrict__ ei, int E) {
    int i = blockIdx.x * blockDim.x + threadIdx.x;
    if (i < E) atomicAdd(&d_deg[ei[E + i]], 1);
}

// single-block scan; folds self-loop (+1) into degrees
__global__ void scan_kernel(int N) {
    __shared__ int sm[1024];
    int t = threadIdx.x;
    int chunk = (N + 1023) >> 10;
    int lo = t * chunk;
    int hi = lo + chunk; if (hi > N) hi = N;
    int sum = 0;
    for (int i = lo; i < hi; i++) sum += d_deg[i] + 1;
    sm[t] = sum;
    __syncthreads();
    #pragma unroll
    for (int o = 1; o < 1024; o <<= 1) {
        int v = (t >= o) ? sm[t - o] : 0;
        __syncthreads();
        sm[t] += v;
        __syncthreads();
    }
    int run = sm[t] - sum;
    for (int i = lo; i < hi; i++) {
        int v = d_deg[i] + 1;
        d_ptr[i] = run;
        d_work[i] = run;
        d_deg[i] = v;
        run += v;
    }
}

// fill CSR + per-edge exp(leakyrelu(logit))
__global__ void fill_kernel(const int* __restrict__ ei, int E, int N) {
    int i = blockIdx.x * blockDim.x + threadIdx.x;
    int Etot = E + N;
    if (i >= Etot) return;
    int s, d;
    if (i < E) { s = ei[i]; d = ei[E + i]; } else { s = d = i - E; }
    int pos = atomicAdd(&d_work[d], 1);
    d_csr_src[pos] = s;
    float4 as = *(const float4*)(d_asrc + s * HEADS);
    float4 ad = *(const float4*)(d_adst + d * HEADS);
    float4 ev;
    ev.x = __expf(lrelu(as.x + ad.x));
    ev.y = __expf(lrelu(as.y + ad.y));
    ev.z = __expf(lrelu(as.z + ad.z));
    ev.w = __expf(lrelu(as.w + ad.w));
    *(float4*)(d_e + (size_t)pos * HEADS) = ev;
}

// ---------------- fused softmax + aggregate (warp per node) ----------------------
__device__ __forceinline__ void agg_edge(int i, int lane,
                                         float* num_x, float* num_y, float* dn) {
    int s = __ldg(&d_csr_src[i]);
    float4 e = *(const float4*)(d_e + (size_t)i * HEADS);
    const __half2* hs = (const __half2*)(d_hh + (size_t)s * HC);
    float2 f0 = __half22float2(hs[lane]);
    float2 f1 = __half22float2(hs[32 + lane]);
    float2 f2 = __half22float2(hs[64 + lane]);
    float2 f3 = __half22float2(hs[96 + lane]);
    num_x[0] += e.x * f0.x;  num_y[0] += e.x * f0.y;
    num_x[1] += e.y * f1.x;  num_y[1] += e.y * f1.y;
    num_x[2] += e.z * f2.x;  num_y[2] += e.z * f2.y;
    num_x[3] += e.w * f3.x;  num_y[3] += e.w * f3.y;
    dn[0] += e.x; dn[1] += e.y; dn[2] += e.z; dn[3] += e.w;
}

__global__ void aggregate_kernel(const float* __restrict__ bias,
                                 float* __restrict__ out, int N) {
    int w = (blockIdx.x * blockDim.x + threadIdx.x) >> 5;
    int lane = threadIdx.x & 31;
    if (w >= N) return;
    int r0 = d_ptr[w];
    int r1 = r0 + d_deg[w];

    float num_x[4] = {0.f, 0.f, 0.f, 0.f};
    float num_y[4] = {0.f, 0.f, 0.f, 0.f};
    float dn[4] = {0.f, 0.f, 0.f, 0.f};

    int i = r0;
    for (; i + 2 <= r1; i += 2) {
        agg_edge(i, lane, num_x, num_y, dn);
        agg_edge(i + 1, lane, num_x, num_y, dn);
    }
    if (i < r1) agg_edge(i, lane, num_x, num_y, dn);

    float i0 = 1.f / dn[0], i1 = 1.f / dn[1], i2 = 1.f / dn[2], i3 = 1.f / dn[3];
    float vx = (num_x[0] * i0 + num_x[1] * i1 + num_x[2] * i2 + num_x[3] * i3) * 0.25f
             + __ldg(&bias[lane * 2]);
    float vy = (num_y[0] * i0 + num_y[1] * i1 + num_y[2] * i2 + num_y[3] * i3) * 0.25f
             + __ldg(&bias[lane * 2 + 1]);
    float2 o;
    o.x = vx > 0.f ? vx : expm1f(vx);
    o.y = vy > 0.f ? vy : expm1f(vy);
    *(float2*)(out + (size_t)w * CDIM + lane * 2) = o;
}

// ---------------- launch ---------------------------------------------------------
extern "C" void kernel_launch(void* const* d_in, const int* in_sizes, int n_in,
                              void* d_out, int out_size) {
    const float* x       = (const float*)d_in[0];
    const int*   ei      = (const int*)d_in[1];
    const float* W       = (const float*)d_in[2];
    const float* att_src = (const float*)d_in[3];
    const float* att_dst = (const float*)d_in[4];
    const float* bias    = (const float*)d_in[5];
    float* out = (float*)d_out;

    int N = in_sizes[0] / IN_DIM;
    int E = in_sizes[1] / 2;
    int Etot = E + N;

    // one-time host-side stream/event setup (no device allocation; happens on
    // the first (correctness) call, before graph capture)
    static cudaStream_t s2 = nullptr;
    static cudaEvent_t ev_fork = nullptr, ev_join = nullptr;
    if (!s2) {
        cudaStreamCreateWithFlags(&s2, cudaStreamNonBlocking);
        cudaEventCreateWithFlags(&ev_fork, cudaEventDisableTiming);
        cudaEventCreateWithFlags(&ev_join, cudaEventDisableTiming);
    }

    // fork: CSR-degree chain (independent of GEMM) runs on s2
    cudaEventRecord(ev_fork, 0);
    cudaStreamWaitEvent(s2, ev_fork, 0);
    deg_init_kernel<<<(N + 255) / 256, 256, 0, s2>>>(N);
    deg_hist_kernel<<<(E + 255) / 256, 256, 0, s2>>>(ei, E);
    scan_kernel<<<1, 1024, 0, s2>>>(N);
    cudaEventRecord(ev_join, s2);

    // main stream: projection GEMM + fused attention dots
    dim3 ggrid(HC / BN, (N + BM - 1) / BM);
    gemm_kernel<<<ggrid, 256>>>(x, W, att_src, att_dst, N);

    // join: fill needs both GEMM outputs and CSR pointers
    cudaStreamWaitEvent(0, ev_join, 0);
    fill_kernel<<<(Etot + 255) / 256, 256>>>(ei, E, N);

    aggregate_kernel<<<(N * 32 + 255) / 256, 256>>>(bias, out, N);
}

// round 9
// speedup vs baseline: 1.0050x; 1.0050x over previous
#include <cuda_runtime.h>
#include <cuda_bf16.h>
#include <cuda_fp16.h>
#include <math.h>

#define NMAX 50000
#define EMAX 800000
#define ETOTMAX (NMAX + EMAX)
#define IN_DIM 128
#define HC 256
#define HEADS 4
#define CDIM 64
#define NEG_SLOPE 0.2f

// ---------------- scratch ----------------
__device__ __half d_hh[(size_t)NMAX * HC];      // projected features fp16 [N, 256]
__device__ float d_asrc[NMAX * HEADS];
__device__ float d_adst[NMAX * HEADS];
__device__ float d_e[(size_t)ETOTMAX * HEADS];  // per-edge exp(logit), CSR order
__device__ int d_deg[NMAX];
__device__ int d_ptr[NMAX];
__device__ int d_work[NMAX];
__device__ int d_csr_src[ETOTMAX];

__device__ __forceinline__ float lrelu(float v) {
    return v > 0.0f ? v : NEG_SLOPE * v;
}

// ---------------- Kernel 1: SGEMM h = x @ W (FFMA2, 128x64 tile, dbuf) ---------
// (proven r5 version: 8x4 microtile, M-paired FFMA2 accumulators)
#define BM 128
#define BN 64
#define BK 16
#define NKT (IN_DIM / BK)

__global__ void gemm_kernel(const float* __restrict__ A, const float* __restrict__ B,
                            const float* __restrict__ att_src,
                            const float* __restrict__ att_dst, int M) {
    __shared__ float As[2][BK][BM];
    __shared__ float Bs[2][BK][BN];

    int bx = blockIdx.x;             // head (BN == CDIM)
    int by = blockIdx.y;
    int tid = threadIdx.x;
    int tx = tid & 15;
    int ty = tid >> 4;
    int row0 = by * BM;
    int col0 = bx * BN;

    unsigned long long acc[4][4];
    #pragma unroll
    for (int i = 0; i < 4; i++)
        #pragma unroll
        for (int j = 0; j < 4; j++) acc[i][j] = 0ULL;

    int ar = tid >> 1;
    int ac0 = (tid & 1) * 8;
    int br = tid >> 4;
    int bc = (tid & 15) * 4;

    float4 pa0, pa1, pb;

    {
        int grow = row0 + ar;
        if (grow < M) {
            pa0 = *(const float4*)(A + (size_t)grow * IN_DIM + ac0);
            pa1 = *(const float4*)(A + (size_t)grow * IN_DIM + ac0 + 4);
        } else {
            pa0 = make_float4(0.f, 0.f, 0.f, 0.f);
            pa1 = pa0;
        }
        pb = *(const float4*)(B + (size_t)br * HC + col0 + bc);
    }
    As[0][ac0 + 0][ar] = pa0.x; As[0][ac0 + 1][ar] = pa0.y;
    As[0][ac0 + 2][ar] = pa0.z; As[0][ac0 + 3][ar] = pa0.w;
    As[0][ac0 + 4][ar] = pa1.x; As[0][ac0 + 5][ar] = pa1.y;
    As[0][ac0 + 6][ar] = pa1.z; As[0][ac0 + 7][ar] = pa1.w;
    *(float4*)(&Bs[0][br][bc]) = pb;
    __syncthreads();

    #pragma unroll
    for (int kt = 0; kt < NKT; kt++) {
        int cur = kt & 1;
        if (kt < NKT - 1) {
            int k0 = (kt + 1) * BK;
            int grow = row0 + ar;
            if (grow < M) {
                pa0 = *(const float4*)(A + (size_t)grow * IN_DIM + k0 + ac0);
                pa1 = *(const float4*)(A + (size_t)grow * IN_DIM + k0 + ac0 + 4);
            } else {
                pa0 = make_float4(0.f, 0.f, 0.f, 0.f);
                pa1 = pa0;
            }
            pb = *(const float4*)(B + (size_t)(k0 + br) * HC + col0 + bc);
        }

        #pragma unroll
        for (int k = 0; k < BK; k++) {
            const ulonglong2* ap = (const ulonglong2*)(&As[cur][k][ty * 8]);
            ulonglong2 a01 = ap[0];
            ulonglong2 a23 = ap[1];
            unsigned long long a64[4] = {a01.x, a01.y, a23.x, a23.y};
            float4 b4 = *(const float4*)(&Bs[cur][k][tx * 4]);
            float bb[4] = {b4.x, b4.y, b4.z, b4.w};
            unsigned long long bp[4];
            #pragma unroll
            for (int j = 0; j < 4; j++)
                asm("mov.b64 %0, {%1, %1};" : "=l"(bp[j]) : "f"(bb[j]));
            #pragma unroll
            for (int i2 = 0; i2 < 4; i2++)
                #pragma unroll
                for (int j = 0; j < 4; j++)
                    asm("fma.rn.f32x2 %0, %1, %2, %0;"
                        : "+l"(acc[i2][j]) : "l"(a64[i2]), "l"(bp[j]));
        }

        if (kt < NKT - 1) {
            int nb = cur ^ 1;
            As[nb][ac0 + 0][ar] = pa0.x; As[nb][ac0 + 1][ar] = pa0.y;
            As[nb][ac0 + 2][ar] = pa0.z; As[nb][ac0 + 3][ar] = pa0.w;
            As[nb][ac0 + 4][ar] = pa1.x; As[nb][ac0 + 5][ar] = pa1.y;
            As[nb][ac0 + 6][ar] = pa1.z; As[nb][ac0 + 7][ar] = pa1.w;
            *(float4*)(&Bs[nb][br][bc]) = pb;
            __syncthreads();
        }
    }

    float accf[8][4];
    #pragma unroll
    for (int i2 = 0; i2 < 4; i2++)
        #pragma unroll
        for (int j = 0; j < 4; j++) {
            float lo, hi;
            asm("mov.b64 {%0, %1}, %2;" : "=f"(lo), "=f"(hi) : "l"(acc[i2][j]));
            accf[2 * i2][j] = lo;
            accf[2 * i2 + 1][j] = hi;
        }

    #pragma unroll
    for (int rr = 0; rr < 8; rr++) {
        int grow = row0 + ty * 8 + rr;
        if (grow < M) {
            __half2 p0 = __floats2half2_rn(accf[rr][0], accf[rr][1]);
            __half2 p1 = __floats2half2_rn(accf[rr][2], accf[rr][3]);
            uint2 pk;
            pk.x = *(unsigned*)&p0;
            pk.y = *(unsigned*)&p1;
            *(uint2*)(d_hh + (size_t)grow * HC + col0 + tx * 4) = pk;
        }
    }

    int head = bx;
    float sw[4], dw[4];
    #pragma unroll
    for (int j = 0; j < 4; j++) {
        sw[j] = __ldg(&att_src[head * CDIM + tx * 4 + j]);
        dw[j] = __ldg(&att_dst[head * CDIM + tx * 4 + j]);
    }
    #pragma unroll
    for (int rr = 0; rr < 8; rr++) {
        float s = accf[rr][0] * sw[0] + accf[rr][1] * sw[1]
                + accf[rr][2] * sw[2] + accf[rr][3] * sw[3];
        float dd = accf[rr][0] * dw[0] + accf[rr][1] * dw[1]
                 + accf[rr][2] * dw[2] + accf[rr][3] * dw[3];
        #pragma unroll
        for (int o = 1; o < 16; o <<= 1) {
            s  += __shfl_xor_sync(0xFFFFFFFFu, s, o);
            dd += __shfl_xor_sync(0xFFFFFFFFu, dd, o);
        }
        int grow = row0 + ty * 8 + rr;
        if (tx == 0 && grow < M) {
            d_asrc[grow * HEADS + head] = s;
            d_adst[grow * HEADS + head] = dd;
        }
    }
}

// ---------------- CSR build ------------------------------------------------------
__global__ void deg_init_kernel(int N) {
    int i = blockIdx.x * blockDim.x + threadIdx.x;
    if (i < N) d_deg[i] = 0;
}

__global__ void deg_hist_kernel(const int* __restrict__ ei, int E) {
    int i = blockIdx.x * blockDim.x + threadIdx.x;
    if (i < E) atomicAdd(&d_deg[ei[E + i]], 1);
}

// single-block scan; folds self-loop (+1) into degrees
__global__ void scan_kernel(int N) {
    __shared__ int sm[1024];
    int t = threadIdx.x;
    int chunk = (N + 1023) >> 10;
    int lo = t * chunk;
    int hi = lo + chunk; if (hi > N) hi = N;
    int sum = 0;
    for (int i = lo; i < hi; i++) sum += d_deg[i] + 1;
    sm[t] = sum;
    __syncthreads();
    #pragma unroll
    for (int o = 1; o < 1024; o <<= 1) {
        int v = (t >= o) ? sm[t - o] : 0;
        __syncthreads();
        sm[t] += v;
        __syncthreads();
    }
    int run = sm[t] - sum;
    for (int i = lo; i < hi; i++) {
        int v = d_deg[i] + 1;
        d_ptr[i] = run;
        d_work[i] = run;
        d_deg[i] = v;
        run += v;
    }
}

// fill CSR + per-edge exp(leakyrelu(logit))
__global__ void fill_kernel(const int* __restrict__ ei, int E, int N) {
    int i = blockIdx.x * blockDim.x + threadIdx.x;
    int Etot = E + N;
    if (i >= Etot) return;
    int s, d;
    if (i < E) { s = ei[i]; d = ei[E + i]; } else { s = d = i - E; }
    int pos = atomicAdd(&d_work[d], 1);
    d_csr_src[pos] = s;
    float4 as = *(const float4*)(d_asrc + s * HEADS);
    float4 ad = *(const float4*)(d_adst + d * HEADS);
    float4 ev;
    ev.x = __expf(lrelu(as.x + ad.x));
    ev.y = __expf(lrelu(as.y + ad.y));
    ev.z = __expf(lrelu(as.z + ad.z));
    ev.w = __expf(lrelu(as.w + ad.w));
    *(float4*)(d_e + (size_t)pos * HEADS) = ev;
}

// ---------------- fused softmax + aggregate (warp per node) ----------------------
__device__ __forceinline__ void agg_edge(int i, int lane,
                                         float* num_x, float* num_y, float* dn) {
    int s = __ldg(&d_csr_src[i]);
    float4 e = *(const float4*)(d_e + (size_t)i * HEADS);
    const __half2* hs = (const __half2*)(d_hh + (size_t)s * HC);
    float2 f0 = __half22float2(hs[lane]);
    float2 f1 = __half22float2(hs[32 + lane]);
    float2 f2 = __half22float2(hs[64 + lane]);
    float2 f3 = __half22float2(hs[96 + lane]);
    num_x[0] += e.x * f0.x;  num_y[0] += e.x * f0.y;
    num_x[1] += e.y * f1.x;  num_y[1] += e.y * f1.y;
    num_x[2] += e.z * f2.x;  num_y[2] += e.z * f2.y;
    num_x[3] += e.w * f3.x;  num_y[3] += e.w * f3.y;
    dn[0] += e.x; dn[1] += e.y; dn[2] += e.z; dn[3] += e.w;
}

__global__ void aggregate_kernel(const float* __restrict__ bias,
                                 float* __restrict__ out, int N) {
    int w = (blockIdx.x * blockDim.x + threadIdx.x) >> 5;
    int lane = threadIdx.x & 31;
    if (w >= N) return;
    int r0 = d_ptr[w];
    int r1 = r0 + d_deg[w];

    float num_x[4] = {0.f, 0.f, 0.f, 0.f};
    float num_y[4] = {0.f, 0.f, 0.f, 0.f};
    float dn[4] = {0.f, 0.f, 0.f, 0.f};

    int i = r0;
    for (; i + 2 <= r1; i += 2) {
        agg_edge(i, lane, num_x, num_y, dn);
        agg_edge(i + 1, lane, num_x, num_y, dn);
    }
    if (i < r1) agg_edge(i, lane, num_x, num_y, dn);

    float i0 = 1.f / dn[0], i1 = 1.f / dn[1], i2 = 1.f / dn[2], i3 = 1.f / dn[3];
    float vx = (num_x[0] * i0 + num_x[1] * i1 + num_x[2] * i2 + num_x[3] * i3) * 0.25f
             + __ldg(&bias[lane * 2]);
    float vy = (num_y[0] * i0 + num_y[1] * i1 + num_y[2] * i2 + num_y[3] * i3) * 0.25f
             + __ldg(&bias[lane * 2 + 1]);
    float2 o;
    o.x = vx > 0.f ? vx : expm1f(vx);
    o.y = vy > 0.f ? vy : expm1f(vy);
    *(float2*)(out + (size_t)w * CDIM + lane * 2) = o;
}

// ---------------- launch ---------------------------------------------------------
extern "C" void kernel_launch(void* const* d_in, const int* in_sizes, int n_in,
                              void* d_out, int out_size) {
    const float* x       = (const float*)d_in[0];
    const int*   ei      = (const int*)d_in[1];
    const float* W       = (const float*)d_in[2];
    const float* att_src = (const float*)d_in[3];
    const float* att_dst = (const float*)d_in[4];
    const float* bias    = (const float*)d_in[5];
    float* out = (float*)d_out;

    int N = in_sizes[0] / IN_DIM;
    int E = in_sizes[1] / 2;
    int Etot = E + N;

    // one-time host-side stream/event setup (no device allocation; happens on
    // the first (correctness) call, before graph capture)
    static cudaStream_t s2 = nullptr;
    static cudaEvent_t ev_fork = nullptr, ev_join = nullptr;
    if (!s2) {
        cudaStreamCreateWithFlags(&s2, cudaStreamNonBlocking);
        cudaEventCreateWithFlags(&ev_fork, cudaEventDisableTiming);
        cudaEventCreateWithFlags(&ev_join, cudaEventDisableTiming);
    }

    // fork: CSR-degree chain (independent of GEMM) runs on s2
    cudaEventRecord(ev_fork, 0);
    cudaStreamWaitEvent(s2, ev_fork, 0);
    deg_init_kernel<<<(N + 255) / 256, 256, 0, s2>>>(N);
    deg_hist_kernel<<<(E + 255) / 256, 256, 0, s2>>>(ei, E);
    scan_kernel<<<1, 1024, 0, s2>>>(N);
    cudaEventRecord(ev_join, s2);

    // main stream: projection GEMM + fused attention dots
    dim3 ggrid(HC / BN, (N + BM - 1) / BM);
    gemm_kernel<<<ggrid, 256>>>(x, W, att_src, att_dst, N);

    // join: fill needs both GEMM outputs and CSR pointers
    cudaStreamWaitEvent(0, ev_join, 0);
    fill_kernel<<<(Etot + 255) / 256, 256>>>(ei, E, N);

    aggregate_kernel<<<(N * 32 + 255) / 256, 256>>>(bias, out, N);
}

// round 10
// speedup vs baseline: 1.0176x; 1.0126x over previous
#include <cuda_runtime.h>
#include <cuda_bf16.h>
#include <cuda_fp16.h>
#include <math.h>

#define NMAX 50000
#define EMAX 800000
#define ETOTMAX (NMAX + EMAX)
#define IN_DIM 128
#define HC 256
#define HEADS 4
#define CDIM 64
#define NEG_SLOPE 0.2f

// ---------------- scratch ----------------
__device__ __half d_hh[(size_t)NMAX * HC];      // projected features fp16 [N, 256]
__device__ float d_asrc[NMAX * HEADS];
__device__ float d_adst[NMAX * HEADS];
__device__ float d_e[(size_t)ETOTMAX * HEADS];  // per-edge exp(logit), CSR order
__device__ int d_deg[NMAX];
__device__ int d_ptr[NMAX];
__device__ int d_work[NMAX];
__device__ int d_csr_src[ETOTMAX];

__device__ __forceinline__ float lrelu(float v) {
    return v > 0.0f ? v : NEG_SLOPE * v;
}

// ---------------- Kernel 1: SGEMM h = x @ W (FFMA2, 128x128 tile, 8x8 micro) ---
#define BM 128
#define BN 128
#define BK 16
#define NKT (IN_DIM / BK)

__global__ __launch_bounds__(256, 2)
void gemm_kernel(const float* __restrict__ A, const float* __restrict__ B,
                 const float* __restrict__ att_src,
                 const float* __restrict__ att_dst, int M) {
    __shared__ float As[2][BK][BM];   // transposed A tiles
    __shared__ float Bs[2][BK][BN];

    int bx = blockIdx.x;              // 0..1 (two heads per block)
    int by = blockIdx.y;
    int tid = threadIdx.x;
    int tx = tid & 15;                // cols tx*8 .. tx*8+7
    int ty = tid >> 4;                // rows ty*8 .. ty*8+7
    int row0 = by * BM;
    int col0 = bx * BN;

    // acc[i2][j]: packed rows (ty*8+2*i2, +1), col tx*8+j
    unsigned long long acc[4][8];
    #pragma unroll
    for (int i = 0; i < 4; i++)
        #pragma unroll
        for (int j = 0; j < 8; j++) acc[i][j] = 0ULL;

    // A loader: r = tid>>1 (0..127), c0 = (tid&1)*8
    int ar = tid >> 1;
    int ac0 = (tid & 1) * 8;
    // B loader: r = tid>>4 (0..15), c = (tid&15)*8
    int br = tid >> 4;
    int bc = (tid & 15) * 8;

    float4 pa0, pa1, pb0, pb1;

    {
        int grow = row0 + ar;
        if (grow < M) {
            pa0 = *(const float4*)(A + (size_t)grow * IN_DIM + ac0);
            pa1 = *(const float4*)(A + (size_t)grow * IN_DIM + ac0 + 4);
        } else {
            pa0 = make_float4(0.f, 0.f, 0.f, 0.f);
            pa1 = pa0;
        }
        pb0 = *(const float4*)(B + (size_t)br * HC + col0 + bc);
        pb1 = *(const float4*)(B + (size_t)br * HC + col0 + bc + 4);
    }
    As[0][ac0 + 0][ar] = pa0.x; As[0][ac0 + 1][ar] = pa0.y;
    As[0][ac0 + 2][ar] = pa0.z; As[0][ac0 + 3][ar] = pa0.w;
    As[0][ac0 + 4][ar] = pa1.x; As[0][ac0 + 5][ar] = pa1.y;
    As[0][ac0 + 6][ar] = pa1.z; As[0][ac0 + 7][ar] = pa1.w;
    *(float4*)(&Bs[0][br][bc]) = pb0;
    *(float4*)(&Bs[0][br][bc + 4]) = pb1;
    __syncthreads();

    #pragma unroll
    for (int kt = 0; kt < NKT; kt++) {
        int cur = kt & 1;
        if (kt < NKT - 1) {
            int k0 = (kt + 1) * BK;
            int grow = row0 + ar;
            if (grow < M) {
                pa0 = *(const float4*)(A + (size_t)grow * IN_DIM + k0 + ac0);
                pa1 = *(const float4*)(A + (size_t)grow * IN_DIM + k0 + ac0 + 4);
            } else {
                pa0 = make_float4(0.f, 0.f, 0.f, 0.f);
                pa1 = pa0;
            }
            pb0 = *(const float4*)(B + (size_t)(k0 + br) * HC + col0 + bc);
            pb1 = *(const float4*)(B + (size_t)(k0 + br) * HC + col0 + bc + 4);
        }

        #pragma unroll
        for (int k = 0; k < BK; k++) {
            const ulonglong2* ap = (const ulonglong2*)(&As[cur][k][ty * 8]);
            ulonglong2 a01 = ap[0];
            ulonglong2 a23 = ap[1];
            unsigned long long a64[4] = {a01.x, a01.y, a23.x, a23.y};
            float4 b0 = *(const float4*)(&Bs[cur][k][tx * 8]);
            float4 b1 = *(const float4*)(&Bs[cur][k][tx * 8 + 4]);
            float bb[8] = {b0.x, b0.y, b0.z, b0.w, b1.x, b1.y, b1.z, b1.w};
            unsigned long long bp[8];
            #pragma unroll
            for (int j = 0; j < 8; j++)
                asm("mov.b64 %0, {%1, %1};" : "=l"(bp[j]) : "f"(bb[j]));
            #pragma unroll
            for (int i2 = 0; i2 < 4; i2++)
                #pragma unroll
                for (int j = 0; j < 8; j++)
                    asm("fma.rn.f32x2 %0, %1, %2, %0;"
                        : "+l"(acc[i2][j]) : "l"(a64[i2]), "l"(bp[j]));
        }

        if (kt < NKT - 1) {
            int nb = cur ^ 1;
            __syncthreads();
            As[nb][ac0 + 0][ar] = pa0.x; As[nb][ac0 + 1][ar] = pa0.y;
            As[nb][ac0 + 2][ar] = pa0.z; As[nb][ac0 + 3][ar] = pa0.w;
            As[nb][ac0 + 4][ar] = pa1.x; As[nb][ac0 + 5][ar] = pa1.y;
            As[nb][ac0 + 6][ar] = pa1.z; As[nb][ac0 + 7][ar] = pa1.w;
            *(float4*)(&Bs[nb][br][bc]) = pb0;
            *(float4*)(&Bs[nb][br][bc + 4]) = pb1;
            __syncthreads();
        }
    }

    // unpack accumulators: accf[rr][j], rr local row
    float accf[8][8];
    #pragma unroll
    for (int i2 = 0; i2 < 4; i2++)
        #pragma unroll
        for (int j = 0; j < 8; j++) {
            float lo, hi;
            asm("mov.b64 {%0, %1}, %2;" : "=f"(lo), "=f"(hi) : "l"(acc[i2][j]));
            accf[2 * i2][j] = lo;
            accf[2 * i2 + 1][j] = hi;
        }

    // store h fp16: 8 cols per row = one uint4
    #pragma unroll
    for (int rr = 0; rr < 8; rr++) {
        int grow = row0 + ty * 8 + rr;
        if (grow < M) {
            uint4 pk;
            __half2 q0 = __floats2half2_rn(accf[rr][0], accf[rr][1]);
            __half2 q1 = __floats2half2_rn(accf[rr][2], accf[rr][3]);
            __half2 q2 = __floats2half2_rn(accf[rr][4], accf[rr][5]);
            __half2 q3 = __floats2half2_rn(accf[rr][6], accf[rr][7]);
            pk.x = *(unsigned*)&q0; pk.y = *(unsigned*)&q1;
            pk.z = *(unsigned*)&q2; pk.w = *(unsigned*)&q3;
            *(uint4*)(d_hh + (size_t)grow * HC + col0 + tx * 8) = pk;
        }
    }

    // fused att-dot epilogue: thread owns 8 cols of head = bx*2 + (tx>>3)
    int head = bx * 2 + (tx >> 3);
    int cin = (tx & 7) * 8;           // col offset within head
    float sw[8], dw[8];
    #pragma unroll
    for (int j = 0; j < 8; j++) {
        sw[j] = __ldg(&att_src[head * CDIM + cin + j]);
        dw[j] = __ldg(&att_dst[head * CDIM + cin + j]);
    }
    #pragma unroll
    for (int rr = 0; rr < 8; rr++) {
        float s = 0.f, dd = 0.f;
        #pragma unroll
        for (int j = 0; j < 8; j++) {
            s  += accf[rr][j] * sw[j];
            dd += accf[rr][j] * dw[j];
        }
        // reduce across the 8 lanes sharing (ty, head): lane bits 0..2 = tx&7
        #pragma unroll
        for (int o = 1; o < 8; o <<= 1) {
            s  += __shfl_xor_sync(0xFFFFFFFFu, s, o);
            dd += __shfl_xor_sync(0xFFFFFFFFu, dd, o);
        }
        int grow = row0 + ty * 8 + rr;
        if ((tx & 7) == 0 && grow < M) {
            d_asrc[grow * HEADS + head] = s;
            d_adst[grow * HEADS + head] = dd;
        }
    }
}

// ---------------- CSR build ------------------------------------------------------
__global__ void deg_init_kernel(int N) {
    int i = blockIdx.x * blockDim.x + threadIdx.x;
    if (i < N) d_deg[i] = 0;
}

__global__ void deg_hist_kernel(const int* __restrict__ ei, int E) {
    int i = blockIdx.x * blockDim.x + threadIdx.x;
    if (i < E) atomicAdd(&d_deg[ei[E + i]], 1);
}

// single-block scan; folds self-loop (+1) into degrees
__global__ void scan_kernel(int N) {
    __shared__ int sm[1024];
    int t = threadIdx.x;
    int chunk = (N + 1023) >> 10;
    int lo = t * chunk;
    int hi = lo + chunk; if (hi > N) hi = N;
    int sum = 0;
    for (int i = lo; i < hi; i++) sum += d_deg[i] + 1;
    sm[t] = sum;
    __syncthreads();
    #pragma unroll
    for (int o = 1; o < 1024; o <<= 1) {
        int v = (t >= o) ? sm[t - o] : 0;
        __syncthreads();
        sm[t] += v;
        __syncthreads();
    }
    int run = sm[t] - sum;
    for (int i = lo; i < hi; i++) {
        int v = d_deg[i] + 1;
        d_ptr[i] = run;
        d_work[i] = run;
        d_deg[i] = v;
        run += v;
    }
}

// fill CSR + per-edge exp(leakyrelu(logit))
__global__ void fill_kernel(const int* __restrict__ ei, int E, int N) {
    int i = blockIdx.x * blockDim.x + threadIdx.x;
    int Etot = E + N;
    if (i >= Etot) return;
    int s, d;
    if (i < E) { s = ei[i]; d = ei[E + i]; } else { s = d = i - E; }
    int pos = atomicAdd(&d_work[d], 1);
    d_csr_src[pos] = s;
    float4 as = *(const float4*)(d_asrc + s * HEADS);
    float4 ad = *(const float4*)(d_adst + d * HEADS);
    float4 ev;
    ev.x = __expf(lrelu(as.x + ad.x));
    ev.y = __expf(lrelu(as.y + ad.y));
    ev.z = __expf(lrelu(as.z + ad.z));
    ev.w = __expf(lrelu(as.w + ad.w));
    *(float4*)(d_e + (size_t)pos * HEADS) = ev;
}

// ---------------- fused softmax + aggregate (warp per node) ----------------------
__device__ __forceinline__ void agg_edge(int i, int lane,
                                         float* num_x, float* num_y, float* dn) {
    int s = __ldg(&d_csr_src[i]);
    float4 e = *(const float4*)(d_e + (size_t)i * HEADS);
    const __half2* hs = (const __half2*)(d_hh + (size_t)s * HC);
    float2 f0 = __half22float2(hs[lane]);
    float2 f1 = __half22float2(hs[32 + lane]);
    float2 f2 = __half22float2(hs[64 + lane]);
    float2 f3 = __half22float2(hs[96 + lane]);
    num_x[0] += e.x * f0.x;  num_y[0] += e.x * f0.y;
    num_x[1] += e.y * f1.x;  num_y[1] += e.y * f1.y;
    num_x[2] += e.z * f2.x;  num_y[2] += e.z * f2.y;
    num_x[3] += e.w * f3.x;  num_y[3] += e.w * f3.y;
    dn[0] += e.x; dn[1] += e.y; dn[2] += e.z; dn[3] += e.w;
}

__global__ void aggregate_kernel(const float* __restrict__ bias,
                                 float* __restrict__ out, int N) {
    int w = (blockIdx.x * blockDim.x + threadIdx.x) >> 5;
    int lane = threadIdx.x & 31;
    if (w >= N) return;
    int r0 = d_ptr[w];
    int r1 = r0 + d_deg[w];

    float num_x[4] = {0.f, 0.f, 0.f, 0.f};
    float num_y[4] = {0.f, 0.f, 0.f, 0.f};
    float dn[4] = {0.f, 0.f, 0.f, 0.f};

    int i = r0;
    for (; i + 2 <= r1; i += 2) {
        agg_edge(i, lane, num_x, num_y, dn);
        agg_edge(i + 1, lane, num_x, num_y, dn);
    }
    if (i < r1) agg_edge(i, lane, num_x, num_y, dn);

    float i0 = 1.f / dn[0], i1 = 1.f / dn[1], i2 = 1.f / dn[2], i3 = 1.f / dn[3];
    float vx = (num_x[0] * i0 + num_x[1] * i1 + num_x[2] * i2 + num_x[3] * i3) * 0.25f
             + __ldg(&bias[lane * 2]);
    float vy = (num_y[0] * i0 + num_y[1] * i1 + num_y[2] * i2 + num_y[3] * i3) * 0.25f
             + __ldg(&bias[lane * 2 + 1]);
    float2 o;
    o.x = vx > 0.f ? vx : expm1f(vx);
    o.y = vy > 0.f ? vy : expm1f(vy);
    *(float2*)(out + (size_t)w * CDIM + lane * 2) = o;
}

// ---------------- launch ---------------------------------------------------------
extern "C" void kernel_launch(void* const* d_in, const int* in_sizes, int n_in,
                              void* d_out, int out_size) {
    const float* x       = (const float*)d_in[0];
    const int*   ei      = (const int*)d_in[1];
    const float* W       = (const float*)d_in[2];
    const float* att_src = (const float*)d_in[3];
    const float* att_dst = (const float*)d_in[4];
    const float* bias    = (const float*)d_in[5];
    float* out = (float*)d_out;

    int N = in_sizes[0] / IN_DIM;
    int E = in_sizes[1] / 2;
    int Etot = E + N;

    dim3 ggrid(HC / BN, (N + BM - 1) / BM);
    gemm_kernel<<<ggrid, 256>>>(x, W, att_src, att_dst, N);

    deg_init_kernel<<<(N + 255) / 256, 256>>>(N);
    deg_hist_kernel<<<(E + 255) / 256, 256>>>(ei, E);
    scan_kernel<<<1, 1024>>>(N);
    fill_kernel<<<(Etot + 255) / 256, 256>>>(ei, E, N);

    aggregate_kernel<<<(N * 32 + 255) / 256, 256>>>(bias, out, N);
}

// round 11
// speedup vs baseline: 1.5557x; 1.5288x over previous
#include <cuda_runtime.h>
#include <cuda_bf16.h>
#include <cuda_fp16.h>
#include <math.h>

#define NMAX 50000
#define EMAX 800000
#define ETOTMAX (NMAX + EMAX)
#define IN_DIM 128
#define HC 256
#define HEADS 4
#define CDIM 64
#define NEG_SLOPE 0.2f
#define SCAN_B 512

// ---------------- scratch ----------------
__device__ __half d_hh[(size_t)NMAX * HC];      // projected features fp16 [N, 256]
__device__ float d_asrc[NMAX * HEADS];
__device__ float d_adst[NMAX * HEADS];
__device__ float d_e[(size_t)ETOTMAX * HEADS];  // per-edge exp(logit), CSR order
__device__ int d_deg[NMAX];
__device__ int d_ptr[NMAX];
__device__ int d_work[NMAX];
__device__ int d_csr_src[ETOTMAX];
__device__ int d_blocksums[SCAN_B];
__device__ int d_blockoff[SCAN_B];

__device__ __forceinline__ float lrelu(float v) {
    return v > 0.0f ? v : NEG_SLOPE * v;
}

// ---------------- Kernel 1: SGEMM h = x @ W (FFMA2, 128x128 tile, 8x8 micro) ---
#define BM 128
#define BN 128
#define BK 16
#define NKT (IN_DIM / BK)

__global__ __launch_bounds__(256, 2)
void gemm_kernel(const float* __restrict__ A, const float* __restrict__ B,
                 const float* __restrict__ att_src,
                 const float* __restrict__ att_dst, int M) {
    __shared__ float As[2][BK][BM];   // transposed A tiles
    __shared__ float Bs[2][BK][BN];

    int bx = blockIdx.x;              // 0..1 (two heads per block)
    int by = blockIdx.y;
    int tid = threadIdx.x;
    int tx = tid & 15;                // cols tx*8 .. tx*8+7
    int ty = tid >> 4;                // rows ty*8 .. ty*8+7
    int row0 = by * BM;
    int col0 = bx * BN;

    unsigned long long acc[4][8];
    #pragma unroll
    for (int i = 0; i < 4; i++)
        #pragma unroll
        for (int j = 0; j < 8; j++) acc[i][j] = 0ULL;

    int ar = tid >> 1;
    int ac0 = (tid & 1) * 8;
    int br = tid >> 4;
    int bc = (tid & 15) * 8;

    float4 pa0, pa1, pb0, pb1;

    {
        int grow = row0 + ar;
        if (grow < M) {
            pa0 = *(const float4*)(A + (size_t)grow * IN_DIM + ac0);
            pa1 = *(const float4*)(A + (size_t)grow * IN_DIM + ac0 + 4);
        } else {
            pa0 = make_float4(0.f, 0.f, 0.f, 0.f);
            pa1 = pa0;
        }
        pb0 = *(const float4*)(B + (size_t)br * HC + col0 + bc);
        pb1 = *(const float4*)(B + (size_t)br * HC + col0 + bc + 4);
    }
    As[0][ac0 + 0][ar] = pa0.x; As[0][ac0 + 1][ar] = pa0.y;
    As[0][ac0 + 2][ar] = pa0.z; As[0][ac0 + 3][ar] = pa0.w;
    As[0][ac0 + 4][ar] = pa1.x; As[0][ac0 + 5][ar] = pa1.y;
    As[0][ac0 + 6][ar] = pa1.z; As[0][ac0 + 7][ar] = pa1.w;
    *(float4*)(&Bs[0][br][bc]) = pb0;
    *(float4*)(&Bs[0][br][bc + 4]) = pb1;
    __syncthreads();

    #pragma unroll
    for (int kt = 0; kt < NKT; kt++) {
        int cur = kt & 1;
        if (kt < NKT - 1) {
            int k0 = (kt + 1) * BK;
            int grow = row0 + ar;
            if (grow < M) {
                pa0 = *(const float4*)(A + (size_t)grow * IN_DIM + k0 + ac0);
                pa1 = *(const float4*)(A + (size_t)grow * IN_DIM + k0 + ac0 + 4);
            } else {
                pa0 = make_float4(0.f, 0.f, 0.f, 0.f);
                pa1 = pa0;
            }
            pb0 = *(const float4*)(B + (size_t)(k0 + br) * HC + col0 + bc);
            pb1 = *(const float4*)(B + (size_t)(k0 + br) * HC + col0 + bc + 4);
        }

        #pragma unroll
        for (int k = 0; k < BK; k++) {
            const ulonglong2* ap = (const ulonglong2*)(&As[cur][k][ty * 8]);
            ulonglong2 a01 = ap[0];
            ulonglong2 a23 = ap[1];
            unsigned long long a64[4] = {a01.x, a01.y, a23.x, a23.y};
            float4 b0 = *(const float4*)(&Bs[cur][k][tx * 8]);
            float4 b1 = *(const float4*)(&Bs[cur][k][tx * 8 + 4]);
            float bb[8] = {b0.x, b0.y, b0.z, b0.w, b1.x, b1.y, b1.z, b1.w};
            unsigned long long bp[8];
            #pragma unroll
            for (int j = 0; j < 8; j++)
                asm("mov.b64 %0, {%1, %1};" : "=l"(bp[j]) : "f"(bb[j]));
            #pragma unroll
            for (int i2 = 0; i2 < 4; i2++)
                #pragma unroll
                for (int j = 0; j < 8; j++)
                    asm("fma.rn.f32x2 %0, %1, %2, %0;"
                        : "+l"(acc[i2][j]) : "l"(a64[i2]), "l"(bp[j]));
        }

        if (kt < NKT - 1) {
            int nb = cur ^ 1;
            __syncthreads();
            As[nb][ac0 + 0][ar] = pa0.x; As[nb][ac0 + 1][ar] = pa0.y;
            As[nb][ac0 + 2][ar] = pa0.z; As[nb][ac0 + 3][ar] = pa0.w;
            As[nb][ac0 + 4][ar] = pa1.x; As[nb][ac0 + 5][ar] = pa1.y;
            As[nb][ac0 + 6][ar] = pa1.z; As[nb][ac0 + 7][ar] = pa1.w;
            *(float4*)(&Bs[nb][br][bc]) = pb0;
            *(float4*)(&Bs[nb][br][bc + 4]) = pb1;
            __syncthreads();
        }
    }

    float accf[8][8];
    #pragma unroll
    for (int i2 = 0; i2 < 4; i2++)
        #pragma unroll
        for (int j = 0; j < 8; j++) {
            float lo, hi;
            asm("mov.b64 {%0, %1}, %2;" : "=f"(lo), "=f"(hi) : "l"(acc[i2][j]));
            accf[2 * i2][j] = lo;
            accf[2 * i2 + 1][j] = hi;
        }

    #pragma unroll
    for (int rr = 0; rr < 8; rr++) {
        int grow = row0 + ty * 8 + rr;
        if (grow < M) {
            uint4 pk;
            __half2 q0 = __floats2half2_rn(accf[rr][0], accf[rr][1]);
            __half2 q1 = __floats2half2_rn(accf[rr][2], accf[rr][3]);
            __half2 q2 = __floats2half2_rn(accf[rr][4], accf[rr][5]);
            __half2 q3 = __floats2half2_rn(accf[rr][6], accf[rr][7]);
            pk.x = *(unsigned*)&q0; pk.y = *(unsigned*)&q1;
            pk.z = *(unsigned*)&q2; pk.w = *(unsigned*)&q3;
            *(uint4*)(d_hh + (size_t)grow * HC + col0 + tx * 8) = pk;
        }
    }

    int head = bx * 2 + (tx >> 3);
    int cin = (tx & 7) * 8;
    float sw[8], dw[8];
    #pragma unroll
    for (int j = 0; j < 8; j++) {
        sw[j] = __ldg(&att_src[head * CDIM + cin + j]);
        dw[j] = __ldg(&att_dst[head * CDIM + cin + j]);
    }
    #pragma unroll
    for (int rr = 0; rr < 8; rr++) {
        float s = 0.f, dd = 0.f;
        #pragma unroll
        for (int j = 0; j < 8; j++) {
            s  += accf[rr][j] * sw[j];
            dd += accf[rr][j] * dw[j];
        }
        #pragma unroll
        for (int o = 1; o < 8; o <<= 1) {
            s  += __shfl_xor_sync(0xFFFFFFFFu, s, o);
            dd += __shfl_xor_sync(0xFFFFFFFFu, dd, o);
        }
        int grow = row0 + ty * 8 + rr;
        if ((tx & 7) == 0 && grow < M) {
            d_asrc[grow * HEADS + head] = s;
            d_adst[grow * HEADS + head] = dd;
        }
    }
}

// ---------------- CSR build (multi-block scan, proven-fast r5 version) -----------
__global__ void deg_init_kernel(int N) {
    int i = blockIdx.x * blockDim.x + threadIdx.x;
    if (i < N) d_deg[i] = 1;   // self loop
}

__global__ void deg_hist_kernel(const int* __restrict__ ei, int E) {
    int i = blockIdx.x * blockDim.x + threadIdx.x;
    if (i < E) atomicAdd(&d_deg[ei[E + i]], 1);
}

__global__ void scan1_kernel(int N) {
    __shared__ int sm[SCAN_B];
    int b = blockIdx.x, t = threadIdx.x;
    int i = b * SCAN_B + t;
    int v = (i < N) ? d_deg[i] : 0;
    sm[t] = v;
    __syncthreads();
    #pragma unroll
    for (int o = 1; o < SCAN_B; o <<= 1) {
        int x = (t >= o) ? sm[t - o] : 0;
        __syncthreads();
        sm[t] += x;
        __syncthreads();
    }
    if (i < N) d_ptr[i] = sm[t] - v;          // exclusive
    if (t == SCAN_B - 1) d_blocksums[b] = sm[t];
}

__global__ void scan2_kernel(int nblocks) {
    __shared__ int sm[SCAN_B];
    int t = threadIdx.x;
    int v = (t < nblocks) ? d_blocksums[t] : 0;
    sm[t] = v;
    __syncthreads();
    #pragma unroll
    for (int o = 1; o < SCAN_B; o <<= 1) {
        int x = (t >= o) ? sm[t - o] : 0;
        __syncthreads();
        sm[t] += x;
        __syncthreads();
    }
    if (t < nblocks) d_blockoff[t] = sm[t] - v;
}

__global__ void scan3_kernel(int N) {
    int i = blockIdx.x * blockDim.x + threadIdx.x;
    if (i < N) {
        int p = d_ptr[i] + d_blockoff[i / SCAN_B];
        d_ptr[i] = p;
        d_work[i] = p;
    }
}

// fill CSR + per-edge exp(leakyrelu(logit))
__global__ void fill_kernel(const int* __restrict__ ei, int E, int N) {
    int i = blockIdx.x * blockDim.x + threadIdx.x;
    int Etot = E + N;
    if (i >= Etot) return;
    int s, d;
    if (i < E) { s = ei[i]; d = ei[E + i]; } else { s = d = i - E; }
    int pos = atomicAdd(&d_work[d], 1);
    d_csr_src[pos] = s;
    float4 as = *(const float4*)(d_asrc + s * HEADS);
    float4 ad = *(const float4*)(d_adst + d * HEADS);
    float4 ev;
    ev.x = __expf(lrelu(as.x + ad.x));
    ev.y = __expf(lrelu(as.y + ad.y));
    ev.z = __expf(lrelu(as.z + ad.z));
    ev.w = __expf(lrelu(as.w + ad.w));
    *(float4*)(d_e + (size_t)pos * HEADS) = ev;
}

// ---------------- fused softmax + aggregate (warp per node) ----------------------
__device__ __forceinline__ void agg_edge(int i, int lane,
                                         float* num_x, float* num_y, float* dn) {
    int s = __ldg(&d_csr_src[i]);
    float4 e = *(const float4*)(d_e + (size_t)i * HEADS);
    const __half2* hs = (const __half2*)(d_hh + (size_t)s * HC);
    float2 f0 = __half22float2(hs[lane]);
    float2 f1 = __half22float2(hs[32 + lane]);
    float2 f2 = __half22float2(hs[64 + lane]);
    float2 f3 = __half22float2(hs[96 + lane]);
    num_x[0] += e.x * f0.x;  num_y[0] += e.x * f0.y;
    num_x[1] += e.y * f1.x;  num_y[1] += e.y * f1.y;
    num_x[2] += e.z * f2.x;  num_y[2] += e.z * f2.y;
    num_x[3] += e.w * f3.x;  num_y[3] += e.w * f3.y;
    dn[0] += e.x; dn[1] += e.y; dn[2] += e.z; dn[3] += e.w;
}

__global__ void aggregate_kernel(const float* __restrict__ bias,
                                 float* __restrict__ out, int N) {
    int w = (blockIdx.x * blockDim.x + threadIdx.x) >> 5;
    int lane = threadIdx.x & 31;
    if (w >= N) return;
    int r0 = d_ptr[w];
    int r1 = r0 + d_deg[w];

    float num_x[4] = {0.f, 0.f, 0.f, 0.f};
    float num_y[4] = {0.f, 0.f, 0.f, 0.f};
    float dn[4] = {0.f, 0.f, 0.f, 0.f};

    int i = r0;
    for (; i + 2 <= r1; i += 2) {
        agg_edge(i, lane, num_x, num_y, dn);
        agg_edge(i + 1, lane, num_x, num_y, dn);
    }
    if (i < r1) agg_edge(i, lane, num_x, num_y, dn);

    float i0 = 1.f / dn[0], i1 = 1.f / dn[1], i2 = 1.f / dn[2], i3 = 1.f / dn[3];
    float vx = (num_x[0] * i0 + num_x[1] * i1 + num_x[2] * i2 + num_x[3] * i3) * 0.25f
             + __ldg(&bias[lane * 2]);
    float vy = (num_y[0] * i0 + num_y[1] * i1 + num_y[2] * i2 + num_y[3] * i3) * 0.25f
             + __ldg(&bias[lane * 2 + 1]);
    float2 o;
    o.x = vx > 0.f ? vx : expm1f(vx);
    o.y = vy > 0.f ? vy : expm1f(vy);
    *(float2*)(out + (size_t)w * CDIM + lane * 2) = o;
}

// ---------------- launch ---------------------------------------------------------
extern "C" void kernel_launch(void* const* d_in, const int* in_sizes, int n_in,
                              void* d_out, int out_size) {
    const float* x       = (const float*)d_in[0];
    const int*   ei      = (const int*)d_in[1];
    const float* W       = (const float*)d_in[2];
    const float* att_src = (const float*)d_in[3];
    const float* att_dst = (const float*)d_in[4];
    const float* bias    = (const float*)d_in[5];
    float* out = (float*)d_out;

    int N = in_sizes[0] / IN_DIM;
    int E = in_sizes[1] / 2;
    int Etot = E + N;
    int nblocks = (N + SCAN_B - 1) / SCAN_B;

    dim3 ggrid(HC / BN, (N + BM - 1) / BM);
    gemm_kernel<<<ggrid, 256>>>(x, W, att_src, att_dst, N);

    deg_init_kernel<<<(N + 255) / 256, 256>>>(N);
    deg_hist_kernel<<<(E + 255) / 256, 256>>>(ei, E);
    scan1_kernel<<<nblocks, SCAN_B>>>(N);
    scan2_kernel<<<1, SCAN_B>>>(nblocks);
    scan3_kernel<<<(N + 255) / 256, 256>>>(N);
    fill_kernel<<<(Etot + 255) / 256, 256>>>(ei, E, N);

    aggregate_kernel<<<(N * 32 + 255) / 256, 256>>>(bias, out, N);
}

// round 12
// speedup vs baseline: 2.2429x; 1.4418x over previous
#include <cuda_runtime.h>
#include <cuda_bf16.h>
#include <cuda_fp16.h>
#include <math.h>

#define NMAX 50000
#define EMAX 800000
#define ETOTMAX (NMAX + EMAX)
#define IN_DIM 128
#define HC 256
#define HEADS 4
#define CDIM 64
#define NEG_SLOPE 0.2f
#define SCAN_B 512

// ---------------- scratch ----------------
__device__ __half d_hh[(size_t)NMAX * HC];      // projected features fp16 [N, 256]
__device__ float d_asrc[NMAX * HEADS];
__device__ float d_adst[NMAX * HEADS];
__device__ float d_e[(size_t)ETOTMAX * HEADS];  // per-edge exp(logit), CSR order
__device__ int d_deg[NMAX];
__device__ int d_ptr[NMAX];
__device__ int d_work[NMAX];
__device__ int d_csr_src[ETOTMAX];
__device__ int d_blocksums[SCAN_B];
__device__ int d_blockoff[SCAN_B];
__device__ unsigned d_wfrag[8 * 4 * 32 * 16];   // W pre-swizzled into mma B-fragment order

__device__ __forceinline__ float lrelu(float v) {
    return v > 0.0f ? v : NEG_SLOPE * v;
}

// ---------------- Kernel 0: W -> fp16 B-fragment layout -------------------------
// layout: idx = ((ki*4 + wn)*32 + lane)*16 + (ni*2 + reg)
//   n = wn*64 + ni*8 + (lane>>2);  k = ki*16 + (lane&3)*2 + reg*8
__global__ void convert_w_kernel(const float* __restrict__ W) {
    int idx = blockIdx.x * blockDim.x + threadIdx.x;
    if (idx >= 8 * 4 * 32 * 16) return;
    int q = idx & 15;
    int lane = (idx >> 4) & 31;
    int wn = (idx >> 9) & 3;
    int ki = idx >> 11;
    int ni = q >> 1;
    int reg = q & 1;
    int n = wn * 64 + ni * 8 + (lane >> 2);
    int k = ki * 16 + (lane & 3) * 2 + reg * 8;
    __half2 p = __floats2half2_rn(W[k * HC + n], W[(k + 1) * HC + n]);
    d_wfrag[idx] = *(unsigned*)&p;
}

// ---------------- Kernel 1: fp16 tensor GEMM h = x @ W + fused att epilogue ----
// 64 rows x 256 cols per block, 256 threads = 8 warps (2M x 4N heads).
// B fragments double-buffered through padded smem (prefetch LDG -> mma -> STS).
#define GBM 64
__global__ __launch_bounds__(256, 2)
void gemm16_kernel(const float* __restrict__ x,
                   const float* __restrict__ att_src,
                   const float* __restrict__ att_dst, int M) {
    __shared__ __half As[GBM][136];    // +8 halves pad for ldmatrix
    __shared__ uint4 Ws[2][640];       // 2 stages x 128 rows x (4+1 pad) uint4

    int tid = threadIdx.x;
    int lane = tid & 31;
    int wid = tid >> 5;
    int warp_m = wid & 1;
    int warp_n = wid >> 1;             // head
    int row0 = blockIdx.x * GBM;

    // ---- load x tile fp32 -> fp16 smem ----
    {
        int r = tid >> 2;
        int q = tid & 3;
        int grow = row0 + r;
        const float4* xr = (const float4*)(x + (size_t)grow * IN_DIM);
        #pragma unroll
        for (int j = 0; j < 8; j++) {
            float4 v = make_float4(0.f, 0.f, 0.f, 0.f);
            if (grow < M) v = xr[q * 8 + j];
            __half2 p0 = __floats2half2_rn(v.x, v.y);
            __half2 p1 = __floats2half2_rn(v.z, v.w);
            uint2 u;
            u.x = *(unsigned*)&p0;
            u.y = *(unsigned*)&p1;
            *(uint2*)(&As[r][q * 32 + j * 4]) = u;
        }
    }

    // ---- prologue: stage B frags for ki=0 ----
    const uint4* wsrc = (const uint4*)d_wfrag;
    {
        int t0 = tid, t1 = tid + 256;
        uint4 p0 = wsrc[t0];
        uint4 p1 = wsrc[t1];
        Ws[0][(t0 >> 2) * 5 + (t0 & 3)] = p0;
        Ws[0][(t1 >> 2) * 5 + (t1 & 3)] = p1;
    }
    __syncthreads();

    float acc[2][8][4];
    #pragma unroll
    for (int mi = 0; mi < 2; mi++)
        #pragma unroll
        for (int ni = 0; ni < 8; ni++)
            #pragma unroll
            for (int c = 0; c < 4; c++) acc[mi][ni][c] = 0.f;

    int mat = lane >> 3;
    int lrow = (mat & 1) * 8 + (lane & 7);
    int lcol = (mat >> 1) * 8;
    int wrow = (warp_n * 32 + lane) * 5;

    #pragma unroll
    for (int ki = 0; ki < 8; ki++) {
        int cur = ki & 1;

        // prefetch next ki's B slice into registers (hidden under mma)
        uint4 pf0, pf1;
        if (ki < 7) {
            int base = (ki + 1) * 512;
            pf0 = wsrc[base + tid];
            pf1 = wsrc[base + tid + 256];
        }

        // B fragments from smem (4x LDS.128, pad-strided)
        unsigned b[16];
        #pragma unroll
        for (int j = 0; j < 4; j++) {
            uint4 v = Ws[cur][wrow + j];
            b[j * 4 + 0] = v.x; b[j * 4 + 1] = v.y;
            b[j * 4 + 2] = v.z; b[j * 4 + 3] = v.w;
        }
        // A fragments via ldmatrix.x4
        unsigned a[2][4];
        #pragma unroll
        for (int mi = 0; mi < 2; mi++) {
            int r = warp_m * 32 + mi * 16 + lrow;
            unsigned addr = (unsigned)__cvta_generic_to_shared(&As[r][ki * 16 + lcol]);
            asm volatile("ldmatrix.sync.aligned.m8n8.x4.shared.b16 {%0,%1,%2,%3}, [%4];"
                         : "=r"(a[mi][0]), "=r"(a[mi][1]), "=r"(a[mi][2]), "=r"(a[mi][3])
                         : "r"(addr));
        }
        #pragma unroll
        for (int mi = 0; mi < 2; mi++)
            #pragma unroll
            for (int ni = 0; ni < 8; ni++)
                asm volatile(
                    "mma.sync.aligned.m16n8k16.row.col.f32.f16.f16.f32 "
                    "{%0,%1,%2,%3}, {%4,%5,%6,%7}, {%8,%9}, {%0,%1,%2,%3};"
                    : "+f"(acc[mi][ni][0]), "+f"(acc[mi][ni][1]),
                      "+f"(acc[mi][ni][2]), "+f"(acc[mi][ni][3])
                    : "r"(a[mi][0]), "r"(a[mi][1]), "r"(a[mi][2]), "r"(a[mi][3]),
                      "r"(b[ni * 2]), "r"(b[ni * 2 + 1]));

        if (ki < 7) {
            int nb = cur ^ 1;
            Ws[nb][(tid >> 2) * 5 + (tid & 3)] = pf0;
            Ws[nb][((tid + 256) >> 2) * 5 + ((tid + 256) & 3)] = pf1;
            __syncthreads();
        }
    }

    // ---- store h fp16 + fused att-dot epilogue ----
    int g = lane >> 2;
    int tg = lane & 3;
    int head = warp_n;

    float sw[16], dwt[16];
    #pragma unroll
    for (int ni = 0; ni < 8; ni++) {
        int c0 = ni * 8 + tg * 2;
        sw[ni * 2]      = __ldg(&att_src[head * CDIM + c0]);
        sw[ni * 2 + 1]  = __ldg(&att_src[head * CDIM + c0 + 1]);
        dwt[ni * 2]     = __ldg(&att_dst[head * CDIM + c0]);
        dwt[ni * 2 + 1] = __ldg(&att_dst[head * CDIM + c0 + 1]);
    }

    #pragma unroll
    for (int mi = 0; mi < 2; mi++) {
        int ra = row0 + warp_m * 32 + mi * 16 + g;
        int rb = ra + 8;
        float s0 = 0.f, s1 = 0.f, d0 = 0.f, d1 = 0.f;
        #pragma unroll
        for (int ni = 0; ni < 8; ni++) {
            s0 += acc[mi][ni][0] * sw[ni * 2] + acc[mi][ni][1] * sw[ni * 2 + 1];
            s1 += acc[mi][ni][2] * sw[ni * 2] + acc[mi][ni][3] * sw[ni * 2 + 1];
            d0 += acc[mi][ni][0] * dwt[ni * 2] + acc[mi][ni][1] * dwt[ni * 2 + 1];
            d1 += acc[mi][ni][2] * dwt[ni * 2] + acc[mi][ni][3] * dwt[ni * 2 + 1];
            __half2 lo = __floats2half2_rn(acc[mi][ni][0], acc[mi][ni][1]);
            __half2 hi = __floats2half2_rn(acc[mi][ni][2], acc[mi][ni][3]);
            int col = head * CDIM + ni * 8 + tg * 2;
            if (ra < M) *(unsigned*)(d_hh + (size_t)ra * HC + col) = *(unsigned*)&lo;
            if (rb < M) *(unsigned*)(d_hh + (size_t)rb * HC + col) = *(unsigned*)&hi;
        }
        #pragma unroll
        for (int o = 1; o < 4; o <<= 1) {
            s0 += __shfl_xor_sync(0xFFFFFFFFu, s0, o);
            s1 += __shfl_xor_sync(0xFFFFFFFFu, s1, o);
            d0 += __shfl_xor_sync(0xFFFFFFFFu, d0, o);
            d1 += __shfl_xor_sync(0xFFFFFFFFu, d1, o);
        }
        if (tg == 0) {
            if (ra < M) {
                d_asrc[ra * HEADS + head] = s0;
                d_adst[ra * HEADS + head] = d0;
            }
            if (rb < M) {
                d_asrc[rb * HEADS + head] = s1;
                d_adst[rb * HEADS + head] = d1;
            }
        }
    }
}

// ---------------- CSR build (multi-block scan, proven-fast) ----------------------
__global__ void deg_init_kernel(int N) {
    int i = blockIdx.x * blockDim.x + threadIdx.x;
    if (i < N) d_deg[i] = 1;   // self loop
}

__global__ void deg_hist_kernel(const int* __restrict__ ei, int E) {
    int i = blockIdx.x * blockDim.x + threadIdx.x;
    if (i < E) atomicAdd(&d_deg[ei[E + i]], 1);
}

__global__ void scan1_kernel(int N) {
    __shared__ int sm[SCAN_B];
    int b = blockIdx.x, t = threadIdx.x;
    int i = b * SCAN_B + t;
    int v = (i < N) ? d_deg[i] : 0;
    sm[t] = v;
    __syncthreads();
    #pragma unroll
    for (int o = 1; o < SCAN_B; o <<= 1) {
        int x = (t >= o) ? sm[t - o] : 0;
        __syncthreads();
        sm[t] += x;
        __syncthreads();
    }
    if (i < N) d_ptr[i] = sm[t] - v;          // exclusive
    if (t == SCAN_B - 1) d_blocksums[b] = sm[t];
}

__global__ void scan2_kernel(int nblocks) {
    __shared__ int sm[SCAN_B];
    int t = threadIdx.x;
    int v = (t < nblocks) ? d_blocksums[t] : 0;
    sm[t] = v;
    __syncthreads();
    #pragma unroll
    for (int o = 1; o < SCAN_B; o <<= 1) {
        int x = (t >= o) ? sm[t - o] : 0;
        __syncthreads();
        sm[t] += x;
        __syncthreads();
    }
    if (t < nblocks) d_blockoff[t] = sm[t] - v;
}

__global__ void scan3_kernel(int N) {
    int i = blockIdx.x * blockDim.x + threadIdx.x;
    if (i < N) {
        int p = d_ptr[i] + d_blockoff[i / SCAN_B];
        d_ptr[i] = p;
        d_work[i] = p;
    }
}

// fill CSR + per-edge exp(leakyrelu(logit))
__global__ void fill_kernel(const int* __restrict__ ei, int E, int N) {
    int i = blockIdx.x * blockDim.x + threadIdx.x;
    int Etot = E + N;
    if (i >= Etot) return;
    int s, d;
    if (i < E) { s = ei[i]; d = ei[E + i]; } else { s = d = i - E; }
    int pos = atomicAdd(&d_work[d], 1);
    d_csr_src[pos] = s;
    float4 as = *(const float4*)(d_asrc + s * HEADS);
    float4 ad = *(const float4*)(d_adst + d * HEADS);
    float4 ev;
    ev.x = __expf(lrelu(as.x + ad.x));
    ev.y = __expf(lrelu(as.y + ad.y));
    ev.z = __expf(lrelu(as.z + ad.z));
    ev.w = __expf(lrelu(as.w + ad.w));
    *(float4*)(d_e + (size_t)pos * HEADS) = ev;
}

// ---------------- fused softmax + aggregate (warp per node) ----------------------
__device__ __forceinline__ void agg_edge(int i, int lane,
                                         float* num_x, float* num_y, float* dn) {
    int s = __ldg(&d_csr_src[i]);
    float4 e = *(const float4*)(d_e + (size_t)i * HEADS);
    const __half2* hs = (const __half2*)(d_hh + (size_t)s * HC);
    float2 f0 = __half22float2(hs[lane]);
    float2 f1 = __half22float2(hs[32 + lane]);
    float2 f2 = __half22float2(hs[64 + lane]);
    float2 f3 = __half22float2(hs[96 + lane]);
    num_x[0] += e.x * f0.x;  num_y[0] += e.x * f0.y;
    num_x[1] += e.y * f1.x;  num_y[1] += e.y * f1.y;
    num_x[2] += e.z * f2.x;  num_y[2] += e.z * f2.y;
    num_x[3] += e.w * f3.x;  num_y[3] += e.w * f3.y;
    dn[0] += e.x; dn[1] += e.y; dn[2] += e.z; dn[3] += e.w;
}

__global__ void aggregate_kernel(const float* __restrict__ bias,
                                 float* __restrict__ out, int N) {
    int w = (blockIdx.x * blockDim.x + threadIdx.x) >> 5;
    int lane = threadIdx.x & 31;
    if (w >= N) return;
    int r0 = d_ptr[w];
    int r1 = r0 + d_deg[w];

    float num_x[4] = {0.f, 0.f, 0.f, 0.f};
    float num_y[4] = {0.f, 0.f, 0.f, 0.f};
    float dn[4] = {0.f, 0.f, 0.f, 0.f};

    int i = r0;
    for (; i + 2 <= r1; i += 2) {
        agg_edge(i, lane, num_x, num_y, dn);
        agg_edge(i + 1, lane, num_x, num_y, dn);
    }
    if (i < r1) agg_edge(i, lane, num_x, num_y, dn);

    float i0 = 1.f / dn[0], i1 = 1.f / dn[1], i2 = 1.f / dn[2], i3 = 1.f / dn[3];
    float vx = (num_x[0] * i0 + num_x[1] * i1 + num_x[2] * i2 + num_x[3] * i3) * 0.25f
             + __ldg(&bias[lane * 2]);
    float vy = (num_y[0] * i0 + num_y[1] * i1 + num_y[2] * i2 + num_y[3] * i3) * 0.25f
             + __ldg(&bias[lane * 2 + 1]);
    float2 o;
    o.x = vx > 0.f ? vx : expm1f(vx);
    o.y = vy > 0.f ? vy : expm1f(vy);
    *(float2*)(out + (size_t)w * CDIM + lane * 2) = o;
}

// ---------------- launch ---------------------------------------------------------
extern "C" void kernel_launch(void* const* d_in, const int* in_sizes, int n_in,
                              void* d_out, int out_size) {
    const float* x       = (const float*)d_in[0];
    const int*   ei      = (const int*)d_in[1];
    const float* W       = (const float*)d_in[2];
    const float* att_src = (const float*)d_in[3];
    const float* att_dst = (const float*)d_in[4];
    const float* bias    = (const float*)d_in[5];
    float* out = (float*)d_out;

    int N = in_sizes[0] / IN_DIM;
    int E = in_sizes[1] / 2;
    int Etot = E + N;
    int nblocks = (N + SCAN_B - 1) / SCAN_B;

    convert_w_kernel<<<(8 * 4 * 32 * 16 + 255) / 256, 256>>>(W);
    gemm16_kernel<<<(N + GBM - 1) / GBM, 256>>>(x, att_src, att_dst, N);

    deg_init_kernel<<<(N + 255) / 256, 256>>>(N);
    deg_hist_kernel<<<(E + 255) / 256, 256>>>(ei, E);
    scan1_kernel<<<nblocks, SCAN_B>>>(N);
    scan2_kernel<<<1, SCAN_B>>>(nblocks);
    scan3_kernel<<<(N + 255) / 256, 256>>>(N);
    fill_kernel<<<(Etot + 255) / 256, 256>>>(ei, E, N);

    aggregate_kernel<<<(N * 32 + 255) / 256, 256>>>(bias, out, N);
}